// round 17
// baseline (speedup 1.0000x reference)
#include <cuda_runtime.h>
#include <cuda_fp16.h>
#include <math.h>
#include <stdint.h>

// ---------------- problem constants ----------------
#define B_    2
#define S_    2048
#define DIN   2048
#define DOUT  2048
#define NH    16
#define HD    128
#define LAT   256
#define ROWS  (B_ * S_)            // 4096
#define QK_SCALE  (0.08838834764831845f * 1.4426950408889634f)  // 1/sqrt(hd) * log2(e)

// ---------------- scratch ----------------
__device__ uint32_t g_xp[ROWS * 1024];        // x as fp16 pairs, slot order
__device__ uint32_t g_latp[ROWS * 128];       // latent pairs, slot order
__device__ uint32_t g_ctxp[ROWS * 1024];      // ctx pairs, slot order
__device__ uint32_t g_qh16[32 * 2048 * 64];   // Q fp16 pairs (natural order, scaled)
__device__ uint32_t g_kh16[32 * 2048 * 64];   // K fp16 pairs (slot order per row)
__device__ uint32_t g_vt16[32 * 128 * 1024];  // V transposed row-pair packs
// weights as fp16 pairs, blocked [kt32][ntile][n 128][slot 16]
__device__ uint32_t g_wqp[64 * 16 * 128 * 16];
__device__ uint32_t g_wdkvp[64 * 2 * 128 * 16];
__device__ uint32_t g_wukp[8 * 16 * 128 * 16];
__device__ uint32_t g_wuvp[8 * 16 * 128 * 16];
__device__ uint32_t g_woutp[64 * 16 * 128 * 16];

__device__ __forceinline__ void mma_f16(float* d, const uint32_t* a, const uint32_t* b) {
    asm volatile(
        "mma.sync.aligned.m16n8k16.row.col.f32.f16.f16.f32 "
        "{%0,%1,%2,%3}, {%4,%5,%6,%7}, {%8,%9}, {%0,%1,%2,%3};"
        : "+f"(d[0]), "+f"(d[1]), "+f"(d[2]), "+f"(d[3])
        : "r"(a[0]), "r"(a[1]), "r"(a[2]), "r"(a[3]), "r"(b[0]), "r"(b[1]));
}

// packed-pair slot: pair p -> u32 index so LDS.64 at (kk*8 + 2*tg) yields
// (pair tg, pair tg+4) = mma b0/b1 (or a0/a2).
__device__ __host__ __forceinline__ int ppos(int p) {
    int pp = p & 7;
    int slot = (pp < 4) ? (2 * pp) : (2 * (pp - 4) + 1);
    return ((p >> 3) << 3) + slot;
}

// single-instruction pack: {lo, hi} -> f16x2 (lo in bits [15:0])
__device__ __forceinline__ uint32_t h2pack(float lo, float hi) {
    uint32_t r;
    asm("cvt.rn.f16x2.f32 %0, %1, %2;" : "=r"(r) : "f"(hi), "f"(lo));
    return r;
}

#define CPA16(saddr, gptr) \
    asm volatile("cp.async.cg.shared.global [%0], [%1], 16;" :: "r"(saddr), "l"(gptr))

// ====================================================================
// one-time converters (unchanged)
// ====================================================================
__global__ void convert_x(const float* __restrict__ x, uint32_t* __restrict__ xp) {
    int row = blockIdx.x, t = threadIdx.x;
    const float* src = x + (size_t)row * 2048;
    uint32_t* dst = xp + (size_t)row * 1024;
#pragma unroll
    for (int j = 0; j < 2; j++) {
        int c = (t + 256 * j) * 4;
        float4 v = *(const float4*)(src + c);
        int p = c >> 1;
        dst[ppos(p)]     = h2pack(v.x, v.y);
        dst[ppos(p + 1)] = h2pack(v.z, v.w);
    }
}

#define WST 132
__global__ void convert_w(const float* __restrict__ W, uint32_t* __restrict__ Bp, int N) {
    __shared__ __align__(16) float stage[32 * WST];
    int kt = blockIdx.y, ntile = blockIdx.x, t = threadIdx.x;
    int NT = N >> 7;
    int r = t >> 5, c = (t & 31) * 4;
    const float* src = W + (size_t)(kt * 32) * N + ntile * 128;
#pragma unroll
    for (int i = 0; i < 4; i++)
        *(float4*)&stage[(r + 8 * i) * WST + c] =
            *(const float4*)(src + (size_t)(r + 8 * i) * N + c);
    __syncthreads();
    uint32_t* dst = Bp + ((size_t)(kt * NT + ntile) * 128) * 16;
#pragma unroll
    for (int j = 0; j < 8; j++) {
        int id = t + 256 * j;
        int n = id >> 4, s = id & 15;
        int grp = s >> 3, sw = s & 7;
        int pp = (sw & 1) ? ((sw >> 1) + 4) : (sw >> 1);
        int p = grp * 8 + pp;
        dst[n * 16 + s] = h2pack(stage[(2 * p) * WST + n], stage[(2 * p + 1) * WST + n]);
    }
}

// ====================================================================
// fp16 tensor-core GEMM: 128x128 tile, BK=64, 2-stage cp.async,
// 2 CTAs/SM. Half the barriers of the BK=32 version.
// modes: 0 fp32+bias | 1 Q fp16 scaled (natural order) | 2 K fp16 (slot)
//        3 V transposed packs | 4 A-format pairs (slot)
// ====================================================================
#define GS 40   // smem u32 stride per row (32 payload + 8 pad; 40%32==8)
#define GSTG 2  // pipeline stages

__global__ __launch_bounds__(256, 2) void f16_gemm(
    const uint32_t* __restrict__ Ap, int assw,
    const uint32_t* __restrict__ Bp,
    float* __restrict__ C, const float* __restrict__ bias,
    int M, int N, int K, int mode,
    uint32_t* __restrict__ oh)
{
    extern __shared__ uint32_t gsm[];
    uint32_t* As = gsm;                    // [GSTG][128*GS]
    uint32_t* Bs = gsm + GSTG * 128 * GS;  // [GSTG][128*GS]
    const uint32_t sA = (uint32_t)__cvta_generic_to_shared(As);
    const uint32_t sB = (uint32_t)__cvta_generic_to_shared(Bs);

    const int t    = threadIdx.x;
    const int lane = t & 31;
    const int warp = t >> 5;
    const int bm   = blockIdx.y * 128;
    const int NT   = N >> 7;
    const int wm   = (warp >> 1) * 32;
    const int wn   = (warp & 1) * 64;
    const int g    = lane >> 2;
    const int tg   = lane & 3;

    const int lrow = t >> 1;        // 0..127
    const int lhalf = t & 1;        // 0/1: k-halves 0-31 / 32-63

// kt_ indexes 64-k chunks. A: contiguous 32 slots. B: two 16-slot halves
// from consecutive kt32 blocks (2kt_, 2kt_+1), loader parity picks half.
#define GISSUE(kt_, buf_)                                                          \
    {                                                                              \
        const uint32_t* as_ = Ap + (size_t)(bm + lrow) * assw + (kt_) * 32 + lhalf * 16; \
        uint32_t ad_ = sA + ((buf_) * 128 * GS + lrow * GS + lhalf * 16) * 4;      \
        CPA16(ad_, as_);       CPA16(ad_ + 16, as_ + 4);                           \
        CPA16(ad_ + 32, as_ + 8); CPA16(ad_ + 48, as_ + 12);                       \
        const uint32_t* bs_ = Bp + ((size_t)(((kt_) * 2 + lhalf) * NT + blockIdx.x) * 128 + lrow) * 16; \
        uint32_t bd_ = sB + ((buf_) * 128 * GS + lrow * GS + lhalf * 16) * 4;      \
        CPA16(bd_, bs_);       CPA16(bd_ + 16, bs_ + 4);                           \
        CPA16(bd_ + 32, bs_ + 8); CPA16(bd_ + 48, bs_ + 12);                       \
        asm volatile("cp.async.commit_group;");                                    \
    }

    float acc[2][8][4];
#pragma unroll
    for (int mt = 0; mt < 2; mt++)
#pragma unroll
        for (int nt = 0; nt < 8; nt++)
#pragma unroll
            for (int r = 0; r < 4; r++) acc[mt][nt][r] = 0.f;

    const int nk = K >> 6;
    GISSUE(0, 0);

    for (int kt = 0; kt < nk; kt++) {
        const int buf = kt & 1;
        if (kt + 1 < nk) {
            GISSUE(kt + 1, buf ^ 1);
            asm volatile("cp.async.wait_group 1;");
        } else {
            asm volatile("cp.async.wait_group 0;");
        }
        __syncthreads();

        const uint32_t* A0 = As + buf * 128 * GS;
        const uint32_t* B0 = Bs + buf * 128 * GS;
#pragma unroll
        for (int kk = 0; kk < 4; kk++) {
            uint32_t af[2][4], bf[8][2];
#pragma unroll
            for (int mt = 0; mt < 2; mt++) {
                uint2 v0 = *(const uint2*)&A0[(wm + mt * 16 + g) * GS + kk * 8 + 2 * tg];
                uint2 v1 = *(const uint2*)&A0[(wm + mt * 16 + g + 8) * GS + kk * 8 + 2 * tg];
                af[mt][0] = v0.x; af[mt][1] = v1.x;
                af[mt][2] = v0.y; af[mt][3] = v1.y;
            }
#pragma unroll
            for (int nt = 0; nt < 8; nt++) {
                uint2 vb = *(const uint2*)&B0[(wn + nt * 8 + g) * GS + kk * 8 + 2 * tg];
                bf[nt][0] = vb.x; bf[nt][1] = vb.y;
            }
#pragma unroll
            for (int mt = 0; mt < 2; mt++)
#pragma unroll
                for (int nt = 0; nt < 8; nt++)
                    mma_f16(acc[mt][nt], af[mt], bf[nt]);
        }
        __syncthreads();
    }

    // ---------------- epilogues (unchanged) ----------------
    if (mode == 0) {
#pragma unroll
        for (int mt = 0; mt < 2; mt++) {
            int row0 = bm + wm + mt * 16 + g;
#pragma unroll
            for (int nt = 0; nt < 8; nt++) {
                int col = blockIdx.x * 128 + wn + nt * 8 + tg * 2;
                float b0 = 0.f, b1 = 0.f;
                if (bias) { b0 = bias[col]; b1 = bias[col + 1]; }
                float2 v0, v1;
                v0.x = acc[mt][nt][0] + b0;
                v0.y = acc[mt][nt][1] + b1;
                v1.x = acc[mt][nt][2] + b0;
                v1.y = acc[mt][nt][3] + b1;
                *(float2*)(C + (size_t)row0 * N + col)       = v0;
                *(float2*)(C + (size_t)(row0 + 8) * N + col) = v1;
            }
        }
    } else if (mode == 1) {   // Q: single fp16, scaled, natural order
#pragma unroll
        for (int mt = 0; mt < 2; mt++) {
            int row0 = bm + wm + mt * 16 + g;
            int bb = row0 >> 11, seq = row0 & 2047;
#pragma unroll
            for (int nt = 0; nt < 8; nt++) {
                int col  = blockIdx.x * 128 + wn + nt * 8 + tg * 2;
                int hh   = col >> 7;
                int slot = (col & 127) >> 1;
                size_t base = ((size_t)(bb * NH + hh) * 2048 + seq) * 64 + slot;
                oh[base]          = h2pack(acc[mt][nt][0] * QK_SCALE, acc[mt][nt][1] * QK_SCALE);
                oh[base + 8 * 64] = h2pack(acc[mt][nt][2] * QK_SCALE, acc[mt][nt][3] * QK_SCALE);
            }
        }
    } else if (mode == 2) {   // K: single fp16, slot order
#pragma unroll
        for (int mt = 0; mt < 2; mt++) {
            int row0 = bm + wm + mt * 16 + g;
            int bb = row0 >> 11, seq = row0 & 2047;
#pragma unroll
            for (int nt = 0; nt < 8; nt++) {
                int col  = blockIdx.x * 128 + wn + nt * 8 + tg * 2;
                int hh   = col >> 7;
                int slot = ppos((col & 127) >> 1);
                size_t base = ((size_t)(bb * NH + hh) * 2048 + seq) * 64 + slot;
                oh[base]          = h2pack(acc[mt][nt][0], acc[mt][nt][1]);
                oh[base + 8 * 64] = h2pack(acc[mt][nt][2], acc[mt][nt][3]);
            }
        }
    } else if (mode == 3) {  // V transposed row-pair packs
#pragma unroll
        for (int mt = 0; mt < 2; mt++) {
            int row0 = bm + wm + mt * 16 + g;
            int bb = row0 >> 11, seq0 = row0 & 2047;
            int ppA = seq0 >> 1;
            int ppB = (seq0 + 8) >> 1;
            int slotA = (ppA >> 4) * 16 + ppos(ppA & 15);
            int slotB = (ppB >> 4) * 16 + ppos(ppB & 15);
#pragma unroll
            for (int nt = 0; nt < 8; nt++) {
                float o0 = acc[mt][nt][0], o1 = acc[mt][nt][1];
                float o2 = acc[mt][nt][2], o3 = acc[mt][nt][3];
                float q0 = __shfl_xor_sync(0xffffffffu, o0, 4);
                float q1 = __shfl_xor_sync(0xffffffffu, o1, 4);
                float q2 = __shfl_xor_sync(0xffffffffu, o2, 4);
                float q3 = __shfl_xor_sync(0xffffffffu, o3, 4);
                if (!(g & 1)) {
                    int col  = blockIdx.x * 128 + wn + nt * 8 + tg * 2;
                    int hh   = col >> 7;
                    int wcol = col & 127;
                    uint32_t* vb = oh + ((size_t)(bb * NH + hh) * 128 + wcol) * 1024;
                    vb[slotA]        = h2pack(o0, q0);
                    vb[1024 + slotA] = h2pack(o1, q1);
                    vb[slotB]        = h2pack(o2, q2);
                    vb[1024 + slotB] = h2pack(o3, q3);
                }
            }
        }
    } else {  // mode 4: A-format pairs (slot order), row width N/2
        const int sw = N >> 1;
#pragma unroll
        for (int mt = 0; mt < 2; mt++) {
            int row0 = bm + wm + mt * 16 + g;
#pragma unroll
            for (int nt = 0; nt < 8; nt++) {
                int col = blockIdx.x * 128 + wn + nt * 8 + tg * 2;
                int slot = ppos(col >> 1);
                oh[(size_t)row0 * sw + slot]       = h2pack(acc[mt][nt][0], acc[mt][nt][1]);
                oh[(size_t)(row0 + 8) * sw + slot] = h2pack(acc[mt][nt][2], acc[mt][nt][3]);
            }
        }
    }
#undef GISSUE
}

// ====================================================================
// fp16 register-resident causal flash attention, FBN=64.
// Half the tiles/barriers/softmax events of the FBN=32 version.
// ====================================================================
#define FBM 128
#define FBN 64
#define KS 72     // K smem stride (64 payload + 8 pad)
#define VS2 40    // V smem stride (32 payload + 8 pad)
#define FA_U32 (2*64*KS + 2*128*VS2)
#define FA_SMEM_BYTES (FA_U32 * 4)

__global__ __launch_bounds__(256) void flash_attn_cp(
    const uint32_t* __restrict__ Qh_g,
    const uint32_t* __restrict__ Kh_g,
    const uint32_t* __restrict__ Vt_g, uint32_t* __restrict__ Ctxp)
{
    extern __shared__ uint32_t smu[];
    uint32_t* Khs = smu;                     // [2][64][KS]
    uint32_t* Vts = smu + 2 * 64 * KS;       // [2][128][VS2]
    const uint32_t sbase = (uint32_t)__cvta_generic_to_shared(smu);
    const uint32_t sKh = sbase;
    const uint32_t sVt = sbase + 2 * 64 * KS * 4;

    const int t    = threadIdx.x;
    const int lane = t & 31;
    const int warp = t >> 5;
    const int g    = lane >> 2;
    const int tg   = lane & 3;

    const int qt = gridDim.x - 1 - blockIdx.x;
    const int qb = qt * FBM;
    const int bh = blockIdx.y;
    const int b  = bh >> 4;
    const int h  = bh & 15;

    const uint32_t* Khg = Kh_g + (size_t)bh * 2048 * 64;
    const uint32_t* Vgg = Vt_g + (size_t)bh * 128 * 1024;

    const int gr0  = qb + warp * 16 + g;
    const int wmax = qb + warp * 16 + 15;

    uint32_t qh[8][4];
    {
        const uint32_t* qhg = Qh_g + ((size_t)bh * 2048 + gr0) * 64;
#pragma unroll
        for (int kk = 0; kk < 8; kk++) {
            qh[kk][0] = qhg[8 * kk + tg];
            qh[kk][1] = qhg[8 * 64 + 8 * kk + tg];
            qh[kk][2] = qhg[8 * kk + tg + 4];
            qh[kk][3] = qhg[8 * 64 + 8 * kk + tg + 4];
        }
    }

    float oacc[16][4];
#pragma unroll
    for (int nt = 0; nt < 16; nt++)
#pragma unroll
        for (int r = 0; r < 4; r++) oacc[nt][r] = 0.f;
    float m0 = -INFINITY, m1 = -INFINITY;
    float l0 = 0.f, l1 = 0.f;

    // loaders: K 64 rows x 16 chunks; V 128 cols x 8 chunks (each 16B)
#define ISSUE_KV(kb_, buf)                                                        \
    {                                                                             \
        _Pragma("unroll")                                                         \
        for (int i = 0; i < 4; i++) {                                             \
            int idx = t + 256 * i;                                                \
            int kro = idx >> 4, kch = idx & 15;                                   \
            const uint32_t* ksrc = Khg + (size_t)((kb_) + kro) * 64 + kch * 4;    \
            CPA16(sKh + (buf) * (64 * KS * 4) + kro * (KS * 4) + kch * 16, ksrc); \
        }                                                                         \
        _Pragma("unroll")                                                         \
        for (int i = 0; i < 4; i++) {                                             \
            int idx = t + 256 * i;                                                \
            int vco = idx >> 3, vch = idx & 7;                                    \
            const uint32_t* vsrc = Vgg + (size_t)vco * 1024 + ((kb_) >> 1) + vch * 4; \
            CPA16(sVt + (buf) * (128 * VS2 * 4) + vco * (VS2 * 4) + vch * 16, vsrc); \
        }                                                                         \
        asm volatile("cp.async.commit_group;");                                   \
    }

    const int nkt = qb / FBN + 2;   // cover cols up to qb+127

    ISSUE_KV(0, 0);
    asm volatile("cp.async.wait_group 0;");
    __syncthreads();

    for (int kt = 0; kt < nkt; kt++) {
        const int kb  = kt * FBN;
        const int cur = kt & 1;
        const bool more = (kt + 1 < nkt);
        if (more) ISSUE_KV(kb + FBN, cur ^ 1);

        if (kb <= wmax) {
            const uint32_t* khb = Khs + cur * 64 * KS;

            // ---- S = Q K^T, 8 nt chains (reuse distance 8 MMAs) ----
            float s[8][4];
#pragma unroll
            for (int nt = 0; nt < 8; nt++)
#pragma unroll
                for (int r = 0; r < 4; r++) s[nt][r] = 0.f;

#pragma unroll
            for (int kk = 0; kk < 8; kk++) {
                uint32_t bhv[8][2];
#pragma unroll
                for (int nt = 0; nt < 8; nt++) {
                    uint2 bh2 = *(const uint2*)&khb[(nt * 8 + g) * KS + kk * 8 + 2 * tg];
                    bhv[nt][0] = bh2.x; bhv[nt][1] = bh2.y;
                }
#pragma unroll
                for (int nt = 0; nt < 8; nt++) mma_f16(s[nt], qh[kk], bhv[nt]);
            }

            // ---- causal mask ----
            if (kb + FBN - 1 > qb + warp * 16) {
#pragma unroll
                for (int nt = 0; nt < 8; nt++) {
                    int cb = kb + nt * 8 + 2 * tg;
                    if (cb     > gr0)     s[nt][0] = -INFINITY;
                    if (cb + 1 > gr0)     s[nt][1] = -INFINITY;
                    if (cb     > gr0 + 8) s[nt][2] = -INFINITY;
                    if (cb + 1 > gr0 + 8) s[nt][3] = -INFINITY;
                }
            }

            // ---- online softmax (base-2) ----
            float mx0 = -INFINITY, mx1 = -INFINITY;
#pragma unroll
            for (int nt = 0; nt < 8; nt++) {
                mx0 = fmaxf(mx0, fmaxf(s[nt][0], s[nt][1]));
                mx1 = fmaxf(mx1, fmaxf(s[nt][2], s[nt][3]));
            }
            mx0 = fmaxf(mx0, __shfl_xor_sync(0xffffffffu, mx0, 1));
            mx0 = fmaxf(mx0, __shfl_xor_sync(0xffffffffu, mx0, 2));
            mx1 = fmaxf(mx1, __shfl_xor_sync(0xffffffffu, mx1, 1));
            mx1 = fmaxf(mx1, __shfl_xor_sync(0xffffffffu, mx1, 2));

            float nm0 = fmaxf(m0, mx0), nm1 = fmaxf(m1, mx1);
            float f0 = exp2f(m0 - nm0), f1 = exp2f(m1 - nm1);
            m0 = nm0; m1 = nm1;

            uint32_t pa[4][4];   // PV A-fragments, kk' 0..3
            float s0 = 0.f, s1 = 0.f;
#pragma unroll
            for (int nt = 0; nt < 8; nt++) {
                float p0 = exp2f(s[nt][0] - nm0);
                float p1 = exp2f(s[nt][1] - nm0);
                float p2 = exp2f(s[nt][2] - nm1);
                float p3 = exp2f(s[nt][3] - nm1);
                s0 += p0 + p1;
                s1 += p2 + p3;
                pa[nt >> 1][(nt & 1) * 2 + 0] = h2pack(p0, p1);
                pa[nt >> 1][(nt & 1) * 2 + 1] = h2pack(p2, p3);
            }
            l0 = l0 * f0 + s0;
            l1 = l1 * f1 + s1;

            if (!__all_sync(0xffffffffu, (f0 == 1.f) && (f1 == 1.f))) {
#pragma unroll
                for (int nt = 0; nt < 16; nt++) {
                    oacc[nt][0] *= f0; oacc[nt][1] *= f0;
                    oacc[nt][2] *= f1; oacc[nt][3] *= f1;
                }
            }

            // ---- O += P V, kk' 0..3 x nt 0..15 ----
            const uint32_t* vpb = Vts + cur * 128 * VS2;
#pragma unroll
            for (int kk = 0; kk < 4; kk++) {
#pragma unroll
                for (int nt = 0; nt < 16; nt++) {
                    uint2 bv = *(const uint2*)&vpb[(nt * 8 + g) * VS2 + kk * 8 + 2 * tg];
                    uint32_t bb[2] = {bv.x, bv.y};
                    mma_f16(oacc[nt], pa[kk], bb);
                }
            }
        }

        if (more) asm volatile("cp.async.wait_group 0;");
        __syncthreads();
    }

    // ---- epilogue: write ctx as fp16 pairs in A-format ----
    l0 += __shfl_xor_sync(0xffffffffu, l0, 1);
    l0 += __shfl_xor_sync(0xffffffffu, l0, 2);
    l1 += __shfl_xor_sync(0xffffffffu, l1, 1);
    l1 += __shfl_xor_sync(0xffffffffu, l1, 2);
    float inv0 = 1.f / l0, inv1 = 1.f / l1;
    uint32_t* c0 = Ctxp + ((size_t)b * S_ + gr0) * 1024;
    uint32_t* c1 = Ctxp + ((size_t)b * S_ + gr0 + 8) * 1024;
#pragma unroll
    for (int nt = 0; nt < 16; nt++) {
        int colg = h * HD + nt * 8 + 2 * tg;
        int slot = ppos(colg >> 1);
        c0[slot] = h2pack(oacc[nt][0] * inv0, oacc[nt][1] * inv0);
        c1[slot] = h2pack(oacc[nt][2] * inv1, oacc[nt][3] * inv1);
    }
#undef ISSUE_KV
}

// ====================================================================
// launch
// ====================================================================
#define GEMM_SMEM (2 * GSTG * 128 * GS * 4)

extern "C" void kernel_launch(void* const* d_in, const int* in_sizes, int n_in,
                              void* d_out, int out_size)
{
    const float* x    = (const float*)d_in[0];
    const float* Wq   = (const float*)d_in[1];
    const float* Wdkv = (const float*)d_in[2];
    const float* Wuk  = (const float*)d_in[3];
    const float* Wuv  = (const float*)d_in[4];
    const float* Wout = (const float*)d_in[5];
    const float* bout = (const float*)d_in[6];
    float* out = (float*)d_out;

    uint32_t *xp, *latp, *ctxp, *qh, *kh, *vt;
    uint32_t *wqp, *wdkvp, *wukp, *wuvp, *woutp;
    cudaGetSymbolAddress((void**)&xp,    g_xp);
    cudaGetSymbolAddress((void**)&latp,  g_latp);
    cudaGetSymbolAddress((void**)&ctxp,  g_ctxp);
    cudaGetSymbolAddress((void**)&qh,    g_qh16);
    cudaGetSymbolAddress((void**)&kh,    g_kh16);
    cudaGetSymbolAddress((void**)&vt,    g_vt16);
    cudaGetSymbolAddress((void**)&wqp,   g_wqp);
    cudaGetSymbolAddress((void**)&wdkvp, g_wdkvp);
    cudaGetSymbolAddress((void**)&wukp,  g_wukp);
    cudaGetSymbolAddress((void**)&wuvp,  g_wuvp);
    cudaGetSymbolAddress((void**)&woutp, g_woutp);

    cudaFuncSetAttribute(flash_attn_cp,
                         cudaFuncAttributeMaxDynamicSharedMemorySize, FA_SMEM_BYTES);
    cudaFuncSetAttribute(f16_gemm,
                         cudaFuncAttributeMaxDynamicSharedMemorySize, GEMM_SMEM);

    // one-time conversions
    convert_x<<<ROWS, 256>>>(x, xp);
    convert_w<<<dim3(16, 64), 256>>>(Wq,   wqp,   DOUT);
    convert_w<<<dim3(2, 64),  256>>>(Wdkv, wdkvp, LAT);
    convert_w<<<dim3(16, 8),  256>>>(Wuk,  wukp,  DOUT);
    convert_w<<<dim3(16, 8),  256>>>(Wuv,  wuvp,  DOUT);
    convert_w<<<dim3(16, 64), 256>>>(Wout, woutp, DOUT);

    // q = x @ Wq -> Q fp16 (scaled, natural order)
    f16_gemm<<<dim3(16, 32), 256, GEMM_SMEM>>>(
        xp, 1024, wqp, nullptr, nullptr, ROWS, DOUT, DIN, 1, qh);
    // latent = x @ Wdkv -> A-format pairs
    f16_gemm<<<dim3(2, 32), 256, GEMM_SMEM>>>(
        xp, 1024, wdkvp, nullptr, nullptr, ROWS, LAT, DIN, 4, latp);
    // k = lat @ Wuk -> K fp16 (slot order)
    f16_gemm<<<dim3(16, 32), 256, GEMM_SMEM>>>(
        latp, 128, wukp, nullptr, nullptr, ROWS, DOUT, LAT, 2, kh);
    // v = lat @ Wuv -> V transposed packs
    f16_gemm<<<dim3(16, 32), 256, GEMM_SMEM>>>(
        latp, 128, wuvp, nullptr, nullptr, ROWS, DOUT, LAT, 3, vt);
    // attention -> ctx pairs
    flash_attn_cp<<<dim3(S_ / FBM, B_ * NH), 256, FA_SMEM_BYTES>>>(
        qh, kh, vt, ctxp);
    // out = ctx @ Wout + bias (fp32)
    f16_gemm<<<dim3(16, 32), 256, GEMM_SMEM>>>(
        ctxp, 1024, woutp, out, bout, ROWS, DOUT, DOUT, 0, nullptr);
}